// round 4
// baseline (speedup 1.0000x reference)
#include <cuda_runtime.h>

// FiniteDifference: x [B=4, T=16, H=128, W=128, C=16] fp32
// out = concat(dy (d/dH), dx (d/dW), dz (d/dT)); central diff, zero pad.
//
// R4: 256-bit (v8.f32) loads/stores, sm_100+ only. Each thread handles one
// 8-float chunk pair index j (2 chunks per pixel, C=16). Halves the number
// of LSU instructions vs the .128 version to attack the LDG issue floor.
// Phased register use (T+H first, store, then W) keeps occupancy up.

#define NC_TOTAL (4 * 16 * 128 * 128 * 2)   // 2,097,152 v8-chunks per output
// chunk strides: W: +-2, H: +-256, T: +-32768 (in v8 chunks of 8 floats)

struct float8 { float4 a, b; };

__device__ __forceinline__ float8 zero8() {
    float8 z;
    z.a = make_float4(0.f, 0.f, 0.f, 0.f);
    z.b = make_float4(0.f, 0.f, 0.f, 0.f);
    return z;
}

__device__ __forceinline__ float8 ld8(const float* p) {
    float8 v;
    asm("ld.global.nc.v8.f32 {%0,%1,%2,%3,%4,%5,%6,%7}, [%8];"
        : "=f"(v.a.x), "=f"(v.a.y), "=f"(v.a.z), "=f"(v.a.w),
          "=f"(v.b.x), "=f"(v.b.y), "=f"(v.b.z), "=f"(v.b.w)
        : "l"(p));
    return v;
}

__device__ __forceinline__ void st8(float* p, float8 v) {
    asm volatile("st.global.cs.v8.f32 [%0], {%1,%2,%3,%4,%5,%6,%7,%8};"
        :: "l"(p),
           "f"(v.a.x), "f"(v.a.y), "f"(v.a.z), "f"(v.a.w),
           "f"(v.b.x), "f"(v.b.y), "f"(v.b.z), "f"(v.b.w)
        : "memory");
}

__device__ __forceinline__ float8 sub8(float8 p, float8 m) {
    float8 r;
    r.a.x = p.a.x - m.a.x; r.a.y = p.a.y - m.a.y;
    r.a.z = p.a.z - m.a.z; r.a.w = p.a.w - m.a.w;
    r.b.x = p.b.x - m.b.x; r.b.y = p.b.y - m.b.y;
    r.b.z = p.b.z - m.b.z; r.b.w = p.b.w - m.b.w;
    return r;
}

__global__ void __launch_bounds__(256)
fd_kernel(const float* __restrict__ x, float* __restrict__ out)
{
    int j = blockIdx.x * blockDim.x + threadIdx.x;   // v8-chunk index

    int w = (j >> 1)  & 127;
    int h = (j >> 8)  & 127;
    int t = (j >> 15) & 15;

    const float* xj = x + (long long)j * 8;

    // Phase 1: T and H neighbors (4 v8 loads in flight)
    float8 tp = (t < 15)  ? ld8(xj + 32768LL * 8) : zero8();
    float8 tm = (t > 0)   ? ld8(xj - 32768LL * 8) : zero8();
    float8 hp = (h < 127) ? ld8(xj + 256LL * 8)   : zero8();
    float8 hm = (h > 0)   ? ld8(xj - 256LL * 8)   : zero8();

    st8(out + ((long long)(2 * NC_TOTAL) + j) * 8, sub8(tp, tm));  // dz
    st8(out + (long long)j * 8,                    sub8(hp, hm));  // dy

    // Phase 2: W neighbors (registers from phase 1 retired)
    float8 wp = (w < 127) ? ld8(xj + 2LL * 8) : zero8();
    float8 wm = (w > 0)   ? ld8(xj - 2LL * 8) : zero8();

    st8(out + ((long long)NC_TOTAL + j) * 8, sub8(wp, wm));        // dx
}

extern "C" void kernel_launch(void* const* d_in, const int* in_sizes, int n_in,
                              void* d_out, int out_size)
{
    const float* x = (const float*)d_in[0];
    float* out = (float*)d_out;

    const int threads = 256;
    const int blocks = NC_TOTAL / threads;   // 8192
    fd_kernel<<<blocks, threads>>>(x, out);
}